// round 2
// baseline (speedup 1.0000x reference)
#include <cuda_runtime.h>
#include <cuda_bf16.h>

// CrossAttention collapses: K/V are a single visual_features row broadcast over
// all T key positions -> softmax over identical logits is exactly uniform ->
// y[b,t,:] = v[b,:] for every t. So:
//   row[b] = (visual @ Wv + bv) @ Wp + bp ; out[b,t,:] = row[b]
//
// Inputs (metadata order): x(0), visual_features(1), Wq(2), bq(3), Wk(4),
// bk(5), Wv(6), bv(7), Wp(8), bp(9). Only 1,6,7,8,9 are needed.

#define C_DIM 1024
#define B_DIM 4

__device__ float g_vv[B_DIM * C_DIM];   // visual @ Wv + bv
__device__ float g_row[B_DIM * C_DIM];  // g_vv @ Wp + bp

// ---------------------------------------------------------------------------
// GEMV: out[b][j] = sum_i in[b][i] * W[i][j] + bias[j]
// grid = (16 j-tiles of 64, B), block = 256 threads.
// Thread layout: jl = tid % 64 (consecutive j -> coalesced W loads),
//                s  = tid / 64 (4-way split of the i reduction).
// Deterministic fixed-order reduction via smem.
// ---------------------------------------------------------------------------
__global__ void __launch_bounds__(256) gemv1_kernel(
    const float* __restrict__ in, const float* __restrict__ W,
    const float* __restrict__ bias)
{
    const int jt = blockIdx.x;
    const int b  = blockIdx.y;
    const int jl = threadIdx.x & 63;
    const int s  = threadIdx.x >> 6;
    const int j  = jt * 64 + jl;

    const float* __restrict__ inb = in + b * C_DIM;
    const float* __restrict__ Wj  = W + j;

    float acc = 0.f;
    const int i0 = s * 256;
    #pragma unroll 8
    for (int i = 0; i < 256; ++i) {
        acc = fmaf(inb[i0 + i], Wj[(i0 + i) * C_DIM], acc);
    }

    __shared__ float red[4][64];
    red[s][jl] = acc;
    __syncthreads();
    if (s == 0) {
        float r = ((red[0][jl] + red[1][jl]) + (red[2][jl] + red[3][jl])) + bias[j];
        g_vv[b * C_DIM + j] = r;
    }
}

__global__ void __launch_bounds__(256) gemv2_kernel(
    const float* __restrict__ W, const float* __restrict__ bias)
{
    const int jt = blockIdx.x;
    const int b  = blockIdx.y;
    const int jl = threadIdx.x & 63;
    const int s  = threadIdx.x >> 6;
    const int j  = jt * 64 + jl;

    const float* __restrict__ inb = g_vv + b * C_DIM;
    const float* __restrict__ Wj  = W + j;

    float acc = 0.f;
    const int i0 = s * 256;
    #pragma unroll 8
    for (int i = 0; i < 256; ++i) {
        acc = fmaf(inb[i0 + i], Wj[(i0 + i) * C_DIM], acc);
    }

    __shared__ float red[4][64];
    red[s][jl] = acc;
    __syncthreads();
    if (s == 0) {
        float r = ((red[0][jl] + red[1][jl]) + (red[2][jl] + red[3][jl])) + bias[j];
        g_row[b * C_DIM + j] = r;
    }
}

// ---------------------------------------------------------------------------
// Broadcast: out[b][t][c] = g_row[b][c] for all t. float4 writes.
// Total B*T*C/4 = 1,048,576 float4 -> grid 4096 x 256, 1 float4/thread.
// TC4 = T*C/4 = 2^18, C4 = 256.
// ---------------------------------------------------------------------------
__global__ void __launch_bounds__(256) bcast_kernel(float4* __restrict__ out)
{
    const int g  = blockIdx.x * blockDim.x + threadIdx.x;
    const int b  = g >> 18;        // / (1024*256)
    const int c4 = g & 255;        // % (1024/4)
    const float4* __restrict__ r4 = reinterpret_cast<const float4*>(g_row);
    out[g] = r4[b * 256 + c4];
}

extern "C" void kernel_launch(void* const* d_in, const int* in_sizes, int n_in,
                              void* d_out, int out_size)
{
    const float* visual = (const float*)d_in[1];
    const float* Wv     = (const float*)d_in[6];
    const float* bv     = (const float*)d_in[7];
    const float* Wp     = (const float*)d_in[8];
    const float* bp     = (const float*)d_in[9];
    float* out = (float*)d_out;

    dim3 gg(16, B_DIM);
    gemv1_kernel<<<gg, 256>>>(visual, Wv, bv);
    gemv2_kernel<<<gg, 256>>>(Wp, bp);

    // out_size = 4*1024*1024 floats = 1,048,576 float4
    bcast_kernel<<<4096, 256>>>(reinterpret_cast<float4*>(out));
}

// round 6
// speedup vs baseline: 1.2846x; 1.2846x over previous
#include <cuda_runtime.h>
#include <cuda_bf16.h>

// CrossAttention collapse: softmax over identical key logits is exactly uniform
// -> y[b,t,:] = v[b,:] -> out[b,t,:] = ((visual@Wv+bv)@Wp + bp)[b,:].
// K1: vv = visual@Wv+bv (high-parallelism batched GEMV)
// K2: row = vv@Wp+bp, fused with broadcast store of the [B,T,C] output.

#define C_DIM 1024
#define B_DIM 4

__device__ float g_vv[B_DIM * C_DIM];

// ---------------------------------------------------------------------------
// K1: vv[b][j] = sum_i visual[b][i] * Wv[i][j] + bv[j]
// grid = 64 (j-tiles of 16), block = 1024: jl = tid&15 (j), s = tid>>4 (64-way
// i-split, 16 i per thread). 4 batch accumulators per thread (W loaded once).
// Deterministic fixed-order smem tree reduction.
// ---------------------------------------------------------------------------
__global__ void __launch_bounds__(1024) k_vv(
    const float* __restrict__ visual, const float* __restrict__ Wv,
    const float* __restrict__ bv)
{
    __shared__ float vis[B_DIM * C_DIM];        // 16 KB
    __shared__ float red[64][B_DIM][16];        // 16 KB

    const int tid = threadIdx.x;
    #pragma unroll
    for (int p = 0; p < 4; ++p)
        vis[p * 1024 + tid] = visual[p * 1024 + tid];
    __syncthreads();

    const int jl = tid & 15;
    const int s  = tid >> 4;
    const int j  = blockIdx.x * 16 + jl;
    const float* __restrict__ Wj = Wv + j;

    float a0 = 0.f, a1 = 0.f, a2 = 0.f, a3 = 0.f;
    const int i0 = s * 16;
    #pragma unroll
    for (int il = 0; il < 16; ++il) {
        const int i = i0 + il;
        const float w = __ldg(Wj + i * C_DIM);
        a0 = fmaf(vis[i],        w, a0);
        a1 = fmaf(vis[1024 + i], w, a1);
        a2 = fmaf(vis[2048 + i], w, a2);
        a3 = fmaf(vis[3072 + i], w, a3);
    }

    red[s][0][jl] = a0; red[s][1][jl] = a1;
    red[s][2][jl] = a2; red[s][3][jl] = a3;
    __syncthreads();

    #pragma unroll
    for (int off = 32; off >= 1; off >>= 1) {
        if (s < off) {
            #pragma unroll
            for (int b = 0; b < 4; ++b)
                red[s][b][jl] += red[s + off][b][jl];
        }
        __syncthreads();
    }

    if (tid < 64) {
        const int b  = tid >> 4;
        const int jj = tid & 15;
        g_vv[b * C_DIM + blockIdx.x * 16 + jj] =
            red[0][b][jj] + bv[blockIdx.x * 16 + jj];
    }
}

// ---------------------------------------------------------------------------
// K2: row[b][j] = sum_i vv[b][i] * Wp[i][j] + bp[j], then broadcast
// out[b][t][j] = row[b][j] for this block's t-slice.
// grid = (32 j-tiles of 32, 8 t-slices of 128), block = 1024:
// jl = tid&31, s = tid>>5 (32-way i-split, 32 i per thread).
// Row values recomputed per t-slice (Wp tile L2-resident). Each block streams
// a 64 KB output slab -> 256 blocks saturate store bandwidth.
// ---------------------------------------------------------------------------
__global__ void __launch_bounds__(1024) k_row_bcast(
    const float* __restrict__ Wp, const float* __restrict__ bp,
    float4* __restrict__ out4)
{
    __shared__ float vv[B_DIM * C_DIM];         // 16 KB
    __shared__ float red[32][B_DIM][32];        // 16 KB
    __shared__ float4 rowsm[B_DIM][8];          // 32 j as 8 float4 per b

    const int tid = threadIdx.x;
    #pragma unroll
    for (int p = 0; p < 4; ++p)
        vv[p * 1024 + tid] = g_vv[p * 1024 + tid];
    __syncthreads();

    const int jl = tid & 31;
    const int s  = tid >> 5;
    const int bx = blockIdx.x;
    const int j  = bx * 32 + jl;
    const float* __restrict__ Wj = Wp + j;

    float a0 = 0.f, a1 = 0.f, a2 = 0.f, a3 = 0.f;
    const int i0 = s * 32;
    #pragma unroll
    for (int il = 0; il < 32; ++il) {
        const int i = i0 + il;
        const float w = __ldg(Wj + i * C_DIM);
        a0 = fmaf(vv[i],        w, a0);
        a1 = fmaf(vv[1024 + i], w, a1);
        a2 = fmaf(vv[2048 + i], w, a2);
        a3 = fmaf(vv[3072 + i], w, a3);
    }

    red[s][0][jl] = a0; red[s][1][jl] = a1;
    red[s][2][jl] = a2; red[s][3][jl] = a3;
    __syncthreads();

    #pragma unroll
    for (int off = 16; off >= 1; off >>= 1) {
        if (s < off) {
            #pragma unroll
            for (int b = 0; b < 4; ++b)
                red[s][b][jl] += red[s + off][b][jl];
        }
        __syncthreads();
    }

    if (tid < 128) {
        const int b  = tid >> 5;
        const int jj = tid & 31;
        reinterpret_cast<float*>(rowsm)[b * 32 + jj] =
            red[0][b][jj] + bp[bx * 32 + jj];
    }
    __syncthreads();

    // Broadcast store: this block covers t in [ts*128, ts*128+128), all 4 b,
    // its 32 j. 8 threads per (b,t) pair, each stores one float4.
    const int ts = blockIdx.y;
    const int q  = tid & 7;          // float4 index within the 32-j tile
    const int pr = tid >> 3;         // pair index within pass (0..127)
    #pragma unroll
    for (int p = 0; p < 4; ++p) {
        const int pairIdx = p * 128 + pr;       // 0..511
        const int b  = pairIdx >> 7;
        const int t  = ts * 128 + (pairIdx & 127);
        const float4 val = rowsm[b][q];
        out4[(size_t)((b << 10) + t) * 256 + bx * 8 + q] = val;
    }
}

extern "C" void kernel_launch(void* const* d_in, const int* in_sizes, int n_in,
                              void* d_out, int out_size)
{
    const float* visual = (const float*)d_in[1];
    const float* Wv     = (const float*)d_in[6];
    const float* bv     = (const float*)d_in[7];
    const float* Wp     = (const float*)d_in[8];
    const float* bp     = (const float*)d_in[9];

    k_vv<<<64, 1024>>>(visual, Wv, bv);
    k_row_bcast<<<dim3(32, 8), 1024>>>(Wp, bp, reinterpret_cast<float4*>(d_out));
}

// round 10
// speedup vs baseline: 2.0875x; 1.6250x over previous
#include <cuda_runtime.h>
#include <cuda_bf16.h>

// CrossAttention collapse: softmax over identical key logits is exactly uniform
// -> y[b,t,:] = v[b,:] -> out[b,t,:] = ((visual@Wv+bv)@Wp + bp)[b,:].
//
// Split-K fusion: row[b,j] = bp[j] + sum_i vv[b,i]*Wp[i,j]. A block that owns
// an i-chunk of vv emits its partial row contribution immediately:
//   K1: per 8-wide i-chunk c: vv[b,c] (from visual@Wv+bv) then
//       P[c][b][:] = sum_{i in c} vv[b,i]*Wp[i,:]        (128 blocks, no redundancy)
//   K2: row = bp + sum_c P[c], broadcast-store [B,T,C]    (128 blocks)

#define C_DIM 1024
#define B_DIM 4
#define NC    128   // number of i-chunks
#define IC    8     // i per chunk

__device__ float g_P[NC][B_DIM][C_DIM];   // 2 MB partial rows

// ---------------------------------------------------------------------------
// K1: grid = NC blocks, block = 1024.
// Stage A: vv[b][i0..i0+7]: il = tid&7 (i), s = tid>>3 (128-way k-split, 8 k
//          each). Warp-shuffle + fixed-order smem tree reduction.
// Stage B: thread j=tid emits P[c][b][j] = sum_q vv[b,q]*Wp[i0+q][j].
// ---------------------------------------------------------------------------
__global__ void __launch_bounds__(1024) k_part(
    const float* __restrict__ visual, const float* __restrict__ Wv,
    const float* __restrict__ bv,     const float* __restrict__ Wp)
{
    __shared__ float vis[B_DIM * C_DIM];          // 16 KB
    __shared__ float red[32][B_DIM][IC + 1];      // padded vs bank conflicts
    __shared__ float vvsm[B_DIM][IC];

    const int tid = threadIdx.x;
    #pragma unroll
    for (int p = 0; p < 4; ++p)
        vis[p * 1024 + tid] = visual[p * 1024 + tid];
    __syncthreads();

    const int c  = blockIdx.x;
    const int i0 = c * IC;
    const int il = tid & 7;
    const int s  = tid >> 3;       // k-slice 0..127
    const int w  = tid >> 5;       // warp 0..31
    const float* __restrict__ Wcol = Wv + i0 + il;

    float a0 = 0.f, a1 = 0.f, a2 = 0.f, a3 = 0.f;
    #pragma unroll
    for (int kk = 0; kk < 8; ++kk) {
        const int k = s * 8 + kk;
        const float wv = __ldg(Wcol + k * C_DIM);
        a0 = fmaf(vis[k],        wv, a0);
        a1 = fmaf(vis[1024 + k], wv, a1);
        a2 = fmaf(vis[2048 + k], wv, a2);
        a3 = fmaf(vis[3072 + k], wv, a3);
    }
    // intra-warp: lanes L, L+8, L+16, L+24 share il -> reduce in fixed order
    a0 += __shfl_down_sync(0xffffffffu, a0, 16);
    a1 += __shfl_down_sync(0xffffffffu, a1, 16);
    a2 += __shfl_down_sync(0xffffffffu, a2, 16);
    a3 += __shfl_down_sync(0xffffffffu, a3, 16);
    a0 += __shfl_down_sync(0xffffffffu, a0, 8);
    a1 += __shfl_down_sync(0xffffffffu, a1, 8);
    a2 += __shfl_down_sync(0xffffffffu, a2, 8);
    a3 += __shfl_down_sync(0xffffffffu, a3, 8);
    if ((tid & 31) < 8) {
        red[w][0][il] = a0; red[w][1][il] = a1;
        red[w][2][il] = a2; red[w][3][il] = a3;
    }
    __syncthreads();

    // fixed-order tree over the 32 warps (16*32=512 <= 1024 threads: valid)
    #pragma unroll
    for (int off = 16; off >= 1; off >>= 1) {
        if (tid < off * 32) {
            const int w2 = tid >> 5, r = tid & 31, b = r >> 3, il2 = r & 7;
            red[w2][b][il2] += red[w2 + off][b][il2];
        }
        __syncthreads();
    }
    if (tid < 32) {
        const int b = tid >> 3, il2 = tid & 7;
        vvsm[b][il2] = red[0][b][il2] + bv[i0 + il2];
    }
    __syncthreads();

    // Stage B: partial rows for this chunk (coalesced Wp row reads)
    float r0 = 0.f, r1 = 0.f, r2 = 0.f, r3 = 0.f;
    #pragma unroll
    for (int q = 0; q < IC; ++q) {
        const float wp = __ldg(Wp + (i0 + q) * C_DIM + tid);
        r0 = fmaf(vvsm[0][q], wp, r0);
        r1 = fmaf(vvsm[1][q], wp, r1);
        r2 = fmaf(vvsm[2][q], wp, r2);
        r3 = fmaf(vvsm[3][q], wp, r3);
    }
    g_P[c][0][tid] = r0;
    g_P[c][1][tid] = r1;
    g_P[c][2][tid] = r2;
    g_P[c][3][tid] = r3;
}

// ---------------------------------------------------------------------------
// K2: grid = (32 j-tiles of 32, 4 t-slices of 256), block = 1024.
// Reduce 128 chunk-partials (jl = tid&31, s = tid>>5 owns 4 chunks), add bias,
// then stream a 128 KB output slab. Tree uses the per-group (s < off) form:
// each of the 32 s-groups has its own 32 jl threads, inner loop over b, so
// ALL 16 first-level pairs are covered (the tid<off*128 form needed 2048
// threads at off=16 and silently dropped chunks 96..127 -> round-8 failure).
// ---------------------------------------------------------------------------
__global__ void __launch_bounds__(1024) k_row_bcast(
    const float* __restrict__ bp, float4* __restrict__ out4)
{
    __shared__ float red[32][B_DIM][33];   // padded
    __shared__ float4 rowsm[B_DIM][8];     // 32 j as 8 float4 per b

    const int tid = threadIdx.x;
    const int jl  = tid & 31;
    const int s   = tid >> 5;
    const int jt  = blockIdx.x;
    const int j   = jt * 32 + jl;

    float r0 = 0.f, r1 = 0.f, r2 = 0.f, r3 = 0.f;
    #pragma unroll
    for (int cc = 0; cc < 4; ++cc) {
        const int c = s * 4 + cc;
        r0 += g_P[c][0][j];
        r1 += g_P[c][1][j];
        r2 += g_P[c][2][j];
        r3 += g_P[c][3][j];
    }
    red[s][0][jl] = r0; red[s][1][jl] = r1;
    red[s][2][jl] = r2; red[s][3][jl] = r3;
    __syncthreads();

    #pragma unroll
    for (int off = 16; off >= 1; off >>= 1) {
        if (s < off) {
            #pragma unroll
            for (int b = 0; b < 4; ++b)
                red[s][b][jl] += red[s + off][b][jl];
        }
        __syncthreads();
    }
    if (tid < 128) {
        const int b = tid >> 5, jl2 = tid & 31;
        reinterpret_cast<float*>(rowsm)[b * 32 + jl2] =
            red[0][b][jl2] + bp[jt * 32 + jl2];
    }
    __syncthreads();

    // Broadcast store: t in [ts*256, ts*256+256), all 4 b, this tile's 32 j.
    // 8 threads per (b,t) pair; each pass covers 128 pairs; 8 passes.
    const int ts = blockIdx.y;
    const int q  = tid & 7;            // float4 index within the 32-j tile
    const int pr = tid >> 3;           // pair index within pass (0..127)
    #pragma unroll
    for (int p = 0; p < 8; ++p) {
        const int pairIdx = p * 128 + pr;          // 0..1023
        const int b = pairIdx >> 8;
        const int t = ts * 256 + (pairIdx & 255);
        out4[(size_t)((b << 10) + t) * 256 + jt * 8 + q] = rowsm[b][q];
    }
}

extern "C" void kernel_launch(void* const* d_in, const int* in_sizes, int n_in,
                              void* d_out, int out_size)
{
    const float* visual = (const float*)d_in[1];
    const float* Wv     = (const float*)d_in[6];
    const float* bv     = (const float*)d_in[7];
    const float* Wp     = (const float*)d_in[8];
    const float* bp     = (const float*)d_in[9];

    k_part<<<NC, 1024>>>(visual, Wv, bv, Wp);
    k_row_bcast<<<dim3(32, 4), 1024>>>(bp, reinterpret_cast<float4*>(d_out));
}